// round 16
// baseline (speedup 1.0000x reference)
#include <cuda_runtime.h>
#include <cuda_bf16.h>
#include <cuda_fp16.h>
#include <math.h>
#include <stdint.h>

#define NMAX 100000
#define EMAX 1600000
#define DH   128
#define DOUT 64
#define NBLK_MAX ((NMAX + 255) / 256)   /* 391 */

#define ALPHA_C  0.2f
#define BETA1_C  0.6931471805599453f
#define BETA2_C  0.4054651081081644f

// ---------------- static device scratch (all intermediates fp16) ----------------
__device__ __half g_xh0[NMAX * DH];     // h0 fp16: fc1 out, gather+residual source
__device__ __half g_xh1[NMAX * DH];     // x1 fp16: gemm2 out, conv2 gather source
__device__ __half g_f16[NMAX * DH];     // spmm out (f1 then f2), GEMM A source
__device__ int    g_deg_out[NMAX];
__device__ int    g_deg_in [NMAX];
__device__ float  g_rs_out[NMAX];
__device__ float  g_rs_in [NMAX];
__device__ int    g_row_ptr[NMAX + 1];
__device__ int    g_cursor [NMAX];
__device__ int    g_cols   [EMAX];
__device__ int    g_blk_sums[NBLK_MAX + 1];
__device__ float  g_wp1[DH * DH];
__device__ float  g_wf [DH * DOUT];
__device__ float  g_bf [DOUT];

// ---------------- helpers ----------------
__device__ __forceinline__ void fp16_split(float v, __half& hi, __half& lo) {
    hi = __float2half_rn(v);
    lo = __float2half_rn(v - __half2float(hi));
}
__device__ __forceinline__ void mma16h(float* c, const uint32_t* a, uint32_t b0, uint32_t b1) {
    asm("mma.sync.aligned.m16n8k16.row.col.f32.f16.f16.f32 "
        "{%0,%1,%2,%3}, {%4,%5,%6,%7}, {%8,%9}, {%0,%1,%2,%3};"
        : "+f"(c[0]), "+f"(c[1]), "+f"(c[2]), "+f"(c[3])
        : "r"(a[0]), "r"(a[1]), "r"(a[2]), "r"(a[3]), "r"(b0), "r"(b1));
}
__device__ __forceinline__ void ldsm_x4(uint32_t addr, uint32_t* r) {
    asm volatile("ldmatrix.sync.aligned.m8n8.x4.shared.b16 {%0,%1,%2,%3}, [%4];"
                 : "=r"(r[0]), "=r"(r[1]), "=r"(r[2]), "=r"(r[3]) : "r"(addr));
}

// ---------------- setup kernels ----------------
__global__ void prep_weights_kernel(const float* __restrict__ cw1,
                                    const float* __restrict__ cw2,
                                    const float* __restrict__ w2,
                                    const float* __restrict__ cb2,
                                    const float* __restrict__ b2) {
    int k = blockIdx.x, j = threadIdx.x;
    float v = BETA1_C * cw1[k * DH + j];
    if (k == j) v += (1.0f - BETA1_C);
    g_wp1[k * DH + j] = v;
    if (j < DOUT) {
        float s = 0.0f;
        for (int m = 0; m < DH; m++) s += cw2[k * DH + m] * w2[m * DOUT + j];
        g_wf[k * DOUT + j] = BETA2_C * s + (1.0f - BETA2_C) * w2[k * DOUT + j];
        if (k == 0) {
            float t = 0.0f;
            for (int m = 0; m < DH; m++) t += cb2[m] * w2[m * DOUT + j];
            g_bf[j] = t + b2[j];
        }
    }
}

__global__ void zero_deg_kernel(int n) {
    int i = blockIdx.x * blockDim.x + threadIdx.x;
    if (i < n) { g_deg_out[i] = 0; g_deg_in[i] = 0; }
}

__global__ void deg_kernel(const int* __restrict__ src, const int* __restrict__ dst, int E) {
    int e = blockIdx.x * blockDim.x + threadIdx.x;
    if (e < E) {
        atomicAdd(&g_deg_out[src[e]], 1);
        atomicAdd(&g_deg_in [dst[e]], 1);
    }
}

__global__ void rs_blocksum_kernel(int n) {
    __shared__ int warp_s[8];
    int i = blockIdx.x * 256 + threadIdx.x;
    int d_in = 0;
    if (i < n) {
        int d_out = g_deg_out[i];
        d_in = g_deg_in[i];
        g_rs_out[i] = rsqrtf(fmaxf((float)d_out, 1.0f));
        g_rs_in [i] = rsqrtf(fmaxf((float)d_in,  1.0f));
    }
    int v = d_in;
#pragma unroll
    for (int o = 16; o > 0; o >>= 1) v += __shfl_down_sync(0xffffffffu, v, o);
    if ((threadIdx.x & 31) == 0) warp_s[threadIdx.x >> 5] = v;
    __syncthreads();
    if (threadIdx.x < 8) {
        int s = warp_s[threadIdx.x];
#pragma unroll
        for (int o = 4; o > 0; o >>= 1) s += __shfl_down_sync(0xffu, s, o);
        if (threadIdx.x == 0) g_blk_sums[blockIdx.x] = s;
    }
}

__global__ void scan_sums_kernel(int nblk, int n) {
    __shared__ int sh[512];
    int t = threadIdx.x;
    sh[t] = (t < nblk) ? g_blk_sums[t] : 0;
    __syncthreads();
#pragma unroll
    for (int o = 1; o < 512; o <<= 1) {
        int v = (t >= o) ? sh[t - o] : 0;
        __syncthreads();
        sh[t] += v;
        __syncthreads();
    }
    if (t < nblk) g_blk_sums[t] = (t == 0) ? 0 : sh[t - 1];
    if (t == 0) {
        g_blk_sums[nblk] = sh[511];
        g_row_ptr[n]     = sh[511];
    }
}

__global__ void writeptr_kernel(int n) {
    __shared__ int sh[256];
    int t = threadIdx.x;
    int i = blockIdx.x * 256 + t;
    int v = (i < n) ? g_deg_in[i] : 0;
    sh[t] = v;
    __syncthreads();
#pragma unroll
    for (int o = 1; o < 256; o <<= 1) {
        int u = (t >= o) ? sh[t - o] : 0;
        __syncthreads();
        sh[t] += u;
        __syncthreads();
    }
    if (i < n) {
        int off = g_blk_sums[blockIdx.x] + sh[t] - v;
        g_row_ptr[i] = off;
        g_cursor [i] = off;
    }
}

__global__ void fill_kernel(const int* __restrict__ src, const int* __restrict__ dst, int E) {
    int e = blockIdx.x * blockDim.x + threadIdx.x;
    if (e < E) {
        int p = atomicAdd(&g_cursor[dst[e]], 1);
        g_cols[p] = src[e];
    }
}

// ---------------- SpMM + residual (warp per row; fp16 in/out, fp32 accumulate) ----------------
__global__ void __launch_bounds__(256) spmm_kernel(const __half* __restrict__ xg,
                                                   const __half* __restrict__ xr,
                                                   __half* __restrict__ f, int n) {
    int w    = (blockIdx.x * blockDim.x + threadIdx.x) >> 5;
    int lane = threadIdx.x & 31;
    if (w >= n) return;
    int start = g_row_ptr[w];
    int end   = g_row_ptr[w + 1];
    float4 acc = make_float4(0.f, 0.f, 0.f, 0.f);
    for (int j = start; j < end; j += 32) {
        int cnt = end - j; if (cnt > 32) cnt = 32;
        int   c  = 0;
        float sw = 0.0f;
        if (lane < cnt) { c = g_cols[j + lane]; sw = g_rs_out[c]; }
        int t = 0;
        for (; t + 4 <= cnt; t += 4) {
            int   c0 = __shfl_sync(0xffffffffu, c,  t);
            int   c1 = __shfl_sync(0xffffffffu, c,  t + 1);
            int   c2 = __shfl_sync(0xffffffffu, c,  t + 2);
            int   c3 = __shfl_sync(0xffffffffu, c,  t + 3);
            float w0 = __shfl_sync(0xffffffffu, sw, t);
            float w1 = __shfl_sync(0xffffffffu, sw, t + 1);
            float w2 = __shfl_sync(0xffffffffu, sw, t + 2);
            float w3 = __shfl_sync(0xffffffffu, sw, t + 3);
            uint2 r0 = *(const uint2*)(xg + (size_t)c0 * DH + lane * 4);
            uint2 r1 = *(const uint2*)(xg + (size_t)c1 * DH + lane * 4);
            uint2 r2 = *(const uint2*)(xg + (size_t)c2 * DH + lane * 4);
            uint2 r3 = *(const uint2*)(xg + (size_t)c3 * DH + lane * 4);
            float2 a0 = __half22float2(*(const __half2*)&r0.x);
            float2 b0 = __half22float2(*(const __half2*)&r0.y);
            acc.x = fmaf(a0.x, w0, acc.x); acc.y = fmaf(a0.y, w0, acc.y);
            acc.z = fmaf(b0.x, w0, acc.z); acc.w = fmaf(b0.y, w0, acc.w);
            float2 a1 = __half22float2(*(const __half2*)&r1.x);
            float2 b1 = __half22float2(*(const __half2*)&r1.y);
            acc.x = fmaf(a1.x, w1, acc.x); acc.y = fmaf(a1.y, w1, acc.y);
            acc.z = fmaf(b1.x, w1, acc.z); acc.w = fmaf(b1.y, w1, acc.w);
            float2 a2 = __half22float2(*(const __half2*)&r2.x);
            float2 b2 = __half22float2(*(const __half2*)&r2.y);
            acc.x = fmaf(a2.x, w2, acc.x); acc.y = fmaf(a2.y, w2, acc.y);
            acc.z = fmaf(b2.x, w2, acc.z); acc.w = fmaf(b2.y, w2, acc.w);
            float2 a3 = __half22float2(*(const __half2*)&r3.x);
            float2 b3 = __half22float2(*(const __half2*)&r3.y);
            acc.x = fmaf(a3.x, w3, acc.x); acc.y = fmaf(a3.y, w3, acc.y);
            acc.z = fmaf(b3.x, w3, acc.z); acc.w = fmaf(b3.y, w3, acc.w);
        }
        for (; t < cnt; t++) {
            int   cc = __shfl_sync(0xffffffffu, c,  t);
            float ww = __shfl_sync(0xffffffffu, sw, t);
            uint2 raw = *(const uint2*)(xg + (size_t)cc * DH + lane * 4);
            float2 v01 = __half22float2(*(const __half2*)&raw.x);
            float2 v23 = __half22float2(*(const __half2*)&raw.y);
            acc.x = fmaf(v01.x, ww, acc.x);
            acc.y = fmaf(v01.y, ww, acc.y);
            acc.z = fmaf(v23.x, ww, acc.z);
            acc.w = fmaf(v23.y, ww, acc.w);
        }
    }
    float ri = g_rs_in[w] * (1.0f - ALPHA_C);
    uint2 xraw = *(const uint2*)(xr + (size_t)w * DH + lane * 4);
    float2 x01 = __half22float2(*(const __half2*)&xraw.x);
    float2 x23 = __half22float2(*(const __half2*)&xraw.y);
    float o0 = fmaf(acc.x, ri, ALPHA_C * x01.x);
    float o1 = fmaf(acc.y, ri, ALPHA_C * x01.y);
    float o2 = fmaf(acc.z, ri, ALPHA_C * x23.x);
    float o3 = fmaf(acc.w, ri, ALPHA_C * x23.y);
    __half2 h01 = __floats2half2_rn(o0, o1);
    __half2 h23 = __floats2half2_rn(o2, o3);
    *(uint2*)(f + (size_t)w * DH + lane * 4) = make_uint2(*(uint32_t*)&h01, *(uint32_t*)&h23);
}

// ---------------- GEMM: 2-term fp16 MMA, 64-col tile blocks (4 blocks/SM) ----------------
// C[n,NWG] = A[n,128] @ B[128,NWG] + bias.  Block owns a 64x64 output tile.
// NWG=128: even/odd blocks own column halves (persistent over M with stride grid/2).
// B = Bhi + Blo (fp16 split, ~22 mantissa bits). AFP32: stage+round A from fp32.
// WMODE: 0 fp32 C; 2 fp16 C16.
template <int NWG, bool RELU, int WMODE, bool AFP32>
__global__ void __launch_bounds__(256) gemm_f16a_kernel(const void* __restrict__ Avoid,
                                                        const float* __restrict__ B,
                                                        const float* __restrict__ bias,
                                                        float* __restrict__ C,
                                                        __half* __restrict__ C16, int n) {
    constexpr int AW = 68;
    constexpr int BW = 68;
    constexpr bool SPLIT = (NWG == 128);
    extern __shared__ uint32_t smu[];
    uint32_t* As  = smu;                 // 64 rows x 68 (fp16 pairs)
    uint32_t* Bhi = As + 64 * AW;        // 64 cols x 68 ([col][kword], fp16)
    uint32_t* Blo = Bhi + 64 * BW;

    int tid = threadIdx.x;
    int nhalf, mblk, mstep;
    if (SPLIT) { nhalf = blockIdx.x & 1; mblk = blockIdx.x >> 1; mstep = gridDim.x >> 1; }
    else       { nhalf = 0;              mblk = blockIdx.x;      mstep = gridDim.x;      }

    // stage + fp16-split B column-half once, [col][k]
    {
        __half* BhiH = (__half*)Bhi;
        __half* BloH = (__half*)Blo;
        const float* Bc = B + nhalf * 64;
#pragma unroll
        for (int i = 0; i < 32; i++) {
            int idx = tid + i * 256;       // 0..8191
            int k   = idx >> 6;
            int col = idx & 63;
            float v = Bc[(size_t)k * NWG + col];
            __half h, l;
            fp16_split(v, h, l);
            BhiH[col * (BW * 2) + k] = h;
            BloH[col * (BW * 2) + k] = l;
        }
    }

    int warp = tid >> 5, lane = tid & 31;
    int gid  = lane >> 2, tig = lane & 3;
    int wm   = warp & 1;                 // 2 m-halves of 32 rows
    int wn   = warp >> 1;                // 4 n-quarters of 16 cols
    int a_row = (lane & 7) + ((lane >> 3) & 1) * 8;
    int a_kx  = (lane >> 4) * 4;
    int b_col = wn * 16 + (lane & 7) + ((lane >> 4) & 1) * 8;
    int b_kx  = ((lane >> 3) & 1) * 4;
    uint32_t b_off = (uint32_t)(b_col * BW + b_kx) * 4u;

    uint32_t sAs  = (uint32_t)__cvta_generic_to_shared(As);
    uint32_t sBhi = (uint32_t)__cvta_generic_to_shared(Bhi);
    uint32_t sBlo = (uint32_t)__cvta_generic_to_shared(Blo);

    for (int mb = mblk; mb * 64 < n; mb += mstep) {
        int m0 = mb * 64;
        __syncthreads();
        if (AFP32) {
            const float4* A4 = (const float4*)Avoid;
            size_t base4 = (size_t)m0 * (DH / 4);
#pragma unroll
            for (int i = 0; i < 8; i++) {
                int idx = tid + i * 256;
                int row = idx >> 5;
                int c4  = idx & 31;
                float4 v = (m0 + row < n) ? A4[base4 + idx] : make_float4(0.f, 0.f, 0.f, 0.f);
                __half2 p0 = __floats2half2_rn(v.x, v.y);
                __half2 p1 = __floats2half2_rn(v.z, v.w);
                As[row * AW + c4 * 2]     = *(uint32_t*)&p0;
                As[row * AW + c4 * 2 + 1] = *(uint32_t*)&p1;
            }
        } else {
            const uint4* A4h = (const uint4*)Avoid;
            size_t base = (size_t)m0 * 16;
#pragma unroll
            for (int i = 0; i < 4; i++) {
                int idx = tid + i * 256;
                int row = idx >> 4;
                int c8  = idx & 15;
                uint4 v = (m0 + row < n) ? A4h[base + idx] : make_uint4(0u, 0u, 0u, 0u);
                *(uint4*)&As[row * AW + c8 * 4] = v;
            }
        }
        __syncthreads();

        float acc[2][2][4];
#pragma unroll
        for (int mt = 0; mt < 2; mt++)
#pragma unroll
            for (int nt = 0; nt < 2; nt++)
#pragma unroll
                for (int q = 0; q < 4; q++) acc[mt][nt][q] = 0.f;

#pragma unroll
        for (int k0 = 0; k0 < DH; k0 += 16) {
            uint32_t kb = (uint32_t)(k0 >> 1) * 4u;
            uint32_t a[2][4];
#pragma unroll
            for (int mt = 0; mt < 2; mt++) {
                uint32_t ao = (uint32_t)((wm * 32 + mt * 16 + a_row) * AW + a_kx) * 4u + kb;
                ldsm_x4(sAs + ao, a[mt]);
            }
            uint32_t bo = b_off + kb;
            uint32_t bh[4], bl[4];
            ldsm_x4(sBhi + bo, bh);
            ldsm_x4(sBlo + bo, bl);
#pragma unroll
            for (int mt = 0; mt < 2; mt++) {
                mma16h(acc[mt][0], a[mt], bh[0], bh[1]);
                mma16h(acc[mt][0], a[mt], bl[0], bl[1]);
                mma16h(acc[mt][1], a[mt], bh[2], bh[3]);
                mma16h(acc[mt][1], a[mt], bl[2], bl[3]);
            }
        }

#pragma unroll
        for (int mt = 0; mt < 2; mt++) {
            int r0 = m0 + wm * 32 + mt * 16 + gid;
            int r1 = r0 + 8;
#pragma unroll
            for (int nt = 0; nt < 2; nt++) {
                int ncl = wn * 16 + nt * 8 + tig * 2;      // col within 64-tile
                int nc0 = nhalf * 64 + ncl;                 // global col
                float bv0 = bias[nc0], bv1 = bias[nc0 + 1];
                float v0 = acc[mt][nt][0] + bv0;
                float v1 = acc[mt][nt][1] + bv1;
                float v2 = acc[mt][nt][2] + bv0;
                float v3 = acc[mt][nt][3] + bv1;
                if (RELU) {
                    v0 = fmaxf(v0, 0.f); v1 = fmaxf(v1, 0.f);
                    v2 = fmaxf(v2, 0.f); v3 = fmaxf(v3, 0.f);
                }
                if (r0 < n) {
                    if (WMODE != 2) *(float2*)&C[(size_t)r0 * NWG + nc0] = make_float2(v0, v1);
                    if (WMODE != 0) *(__half2*)&C16[(size_t)r0 * NWG + nc0] = __floats2half2_rn(v0, v1);
                }
                if (r1 < n) {
                    if (WMODE != 2) *(float2*)&C[(size_t)r1 * NWG + nc0] = make_float2(v2, v3);
                    if (WMODE != 0) *(__half2*)&C16[(size_t)r1 * NWG + nc0] = __floats2half2_rn(v2, v3);
                }
            }
        }
    }
}

// ---------------- launch ----------------
extern "C" void kernel_launch(void* const* d_in, const int* in_sizes, int n_in,
                              void* d_out, int out_size) {
    const float* feat = (const float*)d_in[0];
    const int*   src  = (const int*)  d_in[1];
    const int*   dst  = (const int*)  d_in[2];
    const float* w1   = (const float*)d_in[3];
    const float* b1   = (const float*)d_in[4];
    const float* cw1  = (const float*)d_in[5];
    const float* cb1  = (const float*)d_in[6];
    const float* cw2  = (const float*)d_in[7];
    const float* cb2  = (const float*)d_in[8];
    const float* w2   = (const float*)d_in[9];
    const float* b2   = (const float*)d_in[10];
    float* out = (float*)d_out;

    int n = in_sizes[0] / DH;   // 100000
    int E = in_sizes[1];        // 1600000

    void *p_xh0, *p_xh1, *p_f16, *p_wp1, *p_wf, *p_bf;
    cudaGetSymbolAddress(&p_xh0, g_xh0);
    cudaGetSymbolAddress(&p_xh1, g_xh1);
    cudaGetSymbolAddress(&p_f16, g_f16);
    cudaGetSymbolAddress(&p_wp1, g_wp1);
    cudaGetSymbolAddress(&p_wf,  g_wf);
    cudaGetSymbolAddress(&p_bf,  g_bf);

    constexpr int SMEMB = (64 * 68 + 2 * 64 * 68) * 4;   // 52224 -> 4 blocks/SM
    cudaFuncSetAttribute(gemm_f16a_kernel<128, true, 2, true>,
                         cudaFuncAttributeMaxDynamicSharedMemorySize, SMEMB);
    cudaFuncSetAttribute(gemm_f16a_kernel<128, true, 2, false>,
                         cudaFuncAttributeMaxDynamicSharedMemorySize, SMEMB);
    cudaFuncSetAttribute(gemm_f16a_kernel<64, false, 0, false>,
                         cudaFuncAttributeMaxDynamicSharedMemorySize, SMEMB);

    int nb   = (n + 255) / 256;
    int eb   = (E + 255) / 256;
    int sb   = (n * 32 + 255) / 256;    // spmm: warp per row
    int nblk = (n + 255) / 256;
    const int PG4 = 592;   // 4 blocks/SM persistent grid

    // One-time stream/event infra (created on the first, uncaptured call).
    static cudaStream_t s_csr = nullptr;
    static cudaEvent_t  ev_fork = nullptr, ev_join = nullptr;
    if (s_csr == nullptr) {
        cudaStreamCreateWithFlags(&s_csr, cudaStreamNonBlocking);
        cudaEventCreateWithFlags(&ev_fork, cudaEventDisableTiming);
        cudaEventCreateWithFlags(&ev_join, cudaEventDisableTiming);
    }

    // ---- fork: CSR build chain concurrent with prep+fc1 ----
    cudaEventRecord(ev_fork, 0);
    cudaStreamWaitEvent(s_csr, ev_fork, 0);

    zero_deg_kernel<<<nb, 256, 0, s_csr>>>(n);
    deg_kernel<<<eb, 256, 0, s_csr>>>(src, dst, E);
    rs_blocksum_kernel<<<nblk, 256, 0, s_csr>>>(n);
    scan_sums_kernel<<<1, 512, 0, s_csr>>>(nblk, n);
    writeptr_kernel<<<nblk, 256, 0, s_csr>>>(n);
    fill_kernel<<<eb, 256, 0, s_csr>>>(src, dst, E);
    cudaEventRecord(ev_join, s_csr);

    // branch A: weight prep + fc1 -> xh0 fp16
    prep_weights_kernel<<<DH, DH>>>(cw1, cw2, w2, cb2, b2);
    gemm_f16a_kernel<128, true, 2, true><<<PG4, 256, SMEMB>>>(feat, w1, b1,
        (float*)nullptr, (__half*)p_xh0, n);

    // ---- join ----
    cudaStreamWaitEvent(0, ev_join, 0);

    // conv1 SpMM: gather xh0, residual xh0 -> f16
    spmm_kernel<<<sb, 256>>>((const __half*)p_xh0, (const __half*)p_xh0, (__half*)p_f16, n);

    // conv1 linear: xh1 = relu(f1 @ W1' + cb1)
    gemm_f16a_kernel<128, true, 2, false><<<PG4, 256, SMEMB>>>((const void*)p_f16,
        (const float*)p_wp1, cb1, (float*)nullptr, (__half*)p_xh1, n);

    // conv2 SpMM: gather xh1, residual xh0 -> f16
    spmm_kernel<<<sb, 256>>>((const __half*)p_xh1, (const __half*)p_xh0, (__half*)p_f16, n);

    // conv2+fc2: out = f2 @ Wf + bf
    gemm_f16a_kernel<64, false, 0, false><<<PG4, 256, SMEMB>>>((const void*)p_f16,
        (const float*)p_wf, (const float*)p_bf, out, (__half*)nullptr, n);
}

// round 17
// speedup vs baseline: 1.0596x; 1.0596x over previous
#include <cuda_runtime.h>
#include <cuda_bf16.h>
#include <cuda_fp16.h>
#include <math.h>
#include <stdint.h>

#define NMAX 100000
#define EMAX 1600000
#define DH   128
#define DOUT 64
#define NBLK_MAX ((NMAX + 255) / 256)   /* 391 */

#define ALPHA_C  0.2f
#define BETA1_C  0.6931471805599453f
#define BETA2_C  0.4054651081081644f

// ---------------- static device scratch (all intermediates fp16) ----------------
__device__ __half g_xh0[NMAX * DH];     // h0 fp16: fc1 out, gather+residual source
__device__ __half g_xh1[NMAX * DH];     // x1 fp16: gemm2 out, conv2 gather source
__device__ __half g_f16[NMAX * DH];     // spmm out (f1 then f2), GEMM A source
__device__ int    g_deg_out[NMAX];
__device__ int    g_deg_in [NMAX];
__device__ float  g_rs_out[NMAX];
__device__ float  g_rs_in [NMAX];
__device__ int    g_row_ptr[NMAX + 1];
__device__ int    g_cursor [NMAX];
__device__ int    g_cols   [EMAX];
__device__ int    g_blk_sums[NBLK_MAX + 1];
__device__ float  g_wp1[DH * DH];
__device__ float  g_wf [DH * DOUT];
__device__ float  g_bf [DOUT];

// ---------------- helpers ----------------
__device__ __forceinline__ void fp16_split(float v, __half& hi, __half& lo) {
    hi = __float2half_rn(v);
    lo = __float2half_rn(v - __half2float(hi));
}
__device__ __forceinline__ void mma16h(float* c, const uint32_t* a, uint32_t b0, uint32_t b1) {
    asm("mma.sync.aligned.m16n8k16.row.col.f32.f16.f16.f32 "
        "{%0,%1,%2,%3}, {%4,%5,%6,%7}, {%8,%9}, {%0,%1,%2,%3};"
        : "+f"(c[0]), "+f"(c[1]), "+f"(c[2]), "+f"(c[3])
        : "r"(a[0]), "r"(a[1]), "r"(a[2]), "r"(a[3]), "r"(b0), "r"(b1));
}
__device__ __forceinline__ void ldsm_x4(uint32_t addr, uint32_t* r) {
    asm volatile("ldmatrix.sync.aligned.m8n8.x4.shared.b16 {%0,%1,%2,%3}, [%4];"
                 : "=r"(r[0]), "=r"(r[1]), "=r"(r[2]), "=r"(r[3]) : "r"(addr));
}

// ---------------- setup kernels ----------------
__global__ void prep_weights_kernel(const float* __restrict__ cw1,
                                    const float* __restrict__ cw2,
                                    const float* __restrict__ w2,
                                    const float* __restrict__ cb2,
                                    const float* __restrict__ b2) {
    int k = blockIdx.x, j = threadIdx.x;
    float v = BETA1_C * cw1[k * DH + j];
    if (k == j) v += (1.0f - BETA1_C);
    g_wp1[k * DH + j] = v;
    if (j < DOUT) {
        float s = 0.0f;
        for (int m = 0; m < DH; m++) s += cw2[k * DH + m] * w2[m * DOUT + j];
        g_wf[k * DOUT + j] = BETA2_C * s + (1.0f - BETA2_C) * w2[k * DOUT + j];
        if (k == 0) {
            float t = 0.0f;
            for (int m = 0; m < DH; m++) t += cb2[m] * w2[m * DOUT + j];
            g_bf[j] = t + b2[j];
        }
    }
}

__global__ void zero_deg_kernel(int n) {
    int i = blockIdx.x * blockDim.x + threadIdx.x;
    if (i < n) { g_deg_out[i] = 0; g_deg_in[i] = 0; }
}

__global__ void deg_kernel(const int* __restrict__ src, const int* __restrict__ dst, int E) {
    int e = blockIdx.x * blockDim.x + threadIdx.x;
    if (e < E) {
        atomicAdd(&g_deg_out[src[e]], 1);
        atomicAdd(&g_deg_in [dst[e]], 1);
    }
}

__global__ void rs_blocksum_kernel(int n) {
    __shared__ int warp_s[8];
    int i = blockIdx.x * 256 + threadIdx.x;
    int d_in = 0;
    if (i < n) {
        int d_out = g_deg_out[i];
        d_in = g_deg_in[i];
        g_rs_out[i] = rsqrtf(fmaxf((float)d_out, 1.0f));
        g_rs_in [i] = rsqrtf(fmaxf((float)d_in,  1.0f));
    }
    int v = d_in;
#pragma unroll
    for (int o = 16; o > 0; o >>= 1) v += __shfl_down_sync(0xffffffffu, v, o);
    if ((threadIdx.x & 31) == 0) warp_s[threadIdx.x >> 5] = v;
    __syncthreads();
    if (threadIdx.x < 8) {
        int s = warp_s[threadIdx.x];
#pragma unroll
        for (int o = 4; o > 0; o >>= 1) s += __shfl_down_sync(0xffu, s, o);
        if (threadIdx.x == 0) g_blk_sums[blockIdx.x] = s;
    }
}

__global__ void scan_sums_kernel(int nblk, int n) {
    __shared__ int sh[512];
    int t = threadIdx.x;
    sh[t] = (t < nblk) ? g_blk_sums[t] : 0;
    __syncthreads();
#pragma unroll
    for (int o = 1; o < 512; o <<= 1) {
        int v = (t >= o) ? sh[t - o] : 0;
        __syncthreads();
        sh[t] += v;
        __syncthreads();
    }
    if (t < nblk) g_blk_sums[t] = (t == 0) ? 0 : sh[t - 1];
    if (t == 0) {
        g_blk_sums[nblk] = sh[511];
        g_row_ptr[n]     = sh[511];
    }
}

__global__ void writeptr_kernel(int n) {
    __shared__ int sh[256];
    int t = threadIdx.x;
    int i = blockIdx.x * 256 + t;
    int v = (i < n) ? g_deg_in[i] : 0;
    sh[t] = v;
    __syncthreads();
#pragma unroll
    for (int o = 1; o < 256; o <<= 1) {
        int u = (t >= o) ? sh[t - o] : 0;
        __syncthreads();
        sh[t] += u;
        __syncthreads();
    }
    if (i < n) {
        int off = g_blk_sums[blockIdx.x] + sh[t] - v;
        g_row_ptr[i] = off;
        g_cursor [i] = off;
    }
}

__global__ void fill_kernel(const int* __restrict__ src, const int* __restrict__ dst, int E) {
    int e = blockIdx.x * blockDim.x + threadIdx.x;
    if (e < E) {
        int p = atomicAdd(&g_cursor[dst[e]], 1);
        g_cols[p] = src[e];
    }
}

// ---------------- SpMM + residual (warp per row; fp16 in/out, fp32 accumulate) ----------------
__global__ void __launch_bounds__(256) spmm_kernel(const __half* __restrict__ xg,
                                                   const __half* __restrict__ xr,
                                                   __half* __restrict__ f, int n) {
    int w    = (blockIdx.x * blockDim.x + threadIdx.x) >> 5;
    int lane = threadIdx.x & 31;
    if (w >= n) return;
    int start = g_row_ptr[w];
    int end   = g_row_ptr[w + 1];
    float4 acc = make_float4(0.f, 0.f, 0.f, 0.f);
    for (int j = start; j < end; j += 32) {
        int cnt = end - j; if (cnt > 32) cnt = 32;
        int   c  = 0;
        float sw = 0.0f;
        if (lane < cnt) { c = g_cols[j + lane]; sw = g_rs_out[c]; }
        int t = 0;
        for (; t + 4 <= cnt; t += 4) {
            int   c0 = __shfl_sync(0xffffffffu, c,  t);
            int   c1 = __shfl_sync(0xffffffffu, c,  t + 1);
            int   c2 = __shfl_sync(0xffffffffu, c,  t + 2);
            int   c3 = __shfl_sync(0xffffffffu, c,  t + 3);
            float w0 = __shfl_sync(0xffffffffu, sw, t);
            float w1 = __shfl_sync(0xffffffffu, sw, t + 1);
            float w2 = __shfl_sync(0xffffffffu, sw, t + 2);
            float w3 = __shfl_sync(0xffffffffu, sw, t + 3);
            uint2 r0 = *(const uint2*)(xg + (size_t)c0 * DH + lane * 4);
            uint2 r1 = *(const uint2*)(xg + (size_t)c1 * DH + lane * 4);
            uint2 r2 = *(const uint2*)(xg + (size_t)c2 * DH + lane * 4);
            uint2 r3 = *(const uint2*)(xg + (size_t)c3 * DH + lane * 4);
            float2 a0 = __half22float2(*(const __half2*)&r0.x);
            float2 b0 = __half22float2(*(const __half2*)&r0.y);
            acc.x = fmaf(a0.x, w0, acc.x); acc.y = fmaf(a0.y, w0, acc.y);
            acc.z = fmaf(b0.x, w0, acc.z); acc.w = fmaf(b0.y, w0, acc.w);
            float2 a1 = __half22float2(*(const __half2*)&r1.x);
            float2 b1 = __half22float2(*(const __half2*)&r1.y);
            acc.x = fmaf(a1.x, w1, acc.x); acc.y = fmaf(a1.y, w1, acc.y);
            acc.z = fmaf(b1.x, w1, acc.z); acc.w = fmaf(b1.y, w1, acc.w);
            float2 a2 = __half22float2(*(const __half2*)&r2.x);
            float2 b2 = __half22float2(*(const __half2*)&r2.y);
            acc.x = fmaf(a2.x, w2, acc.x); acc.y = fmaf(a2.y, w2, acc.y);
            acc.z = fmaf(b2.x, w2, acc.z); acc.w = fmaf(b2.y, w2, acc.w);
            float2 a3 = __half22float2(*(const __half2*)&r3.x);
            float2 b3 = __half22float2(*(const __half2*)&r3.y);
            acc.x = fmaf(a3.x, w3, acc.x); acc.y = fmaf(a3.y, w3, acc.y);
            acc.z = fmaf(b3.x, w3, acc.z); acc.w = fmaf(b3.y, w3, acc.w);
        }
        for (; t < cnt; t++) {
            int   cc = __shfl_sync(0xffffffffu, c,  t);
            float ww = __shfl_sync(0xffffffffu, sw, t);
            uint2 raw = *(const uint2*)(xg + (size_t)cc * DH + lane * 4);
            float2 v01 = __half22float2(*(const __half2*)&raw.x);
            float2 v23 = __half22float2(*(const __half2*)&raw.y);
            acc.x = fmaf(v01.x, ww, acc.x);
            acc.y = fmaf(v01.y, ww, acc.y);
            acc.z = fmaf(v23.x, ww, acc.z);
            acc.w = fmaf(v23.y, ww, acc.w);
        }
    }
    float ri = g_rs_in[w] * (1.0f - ALPHA_C);
    uint2 xraw = *(const uint2*)(xr + (size_t)w * DH + lane * 4);
    float2 x01 = __half22float2(*(const __half2*)&xraw.x);
    float2 x23 = __half22float2(*(const __half2*)&xraw.y);
    float o0 = fmaf(acc.x, ri, ALPHA_C * x01.x);
    float o1 = fmaf(acc.y, ri, ALPHA_C * x01.y);
    float o2 = fmaf(acc.z, ri, ALPHA_C * x23.x);
    float o3 = fmaf(acc.w, ri, ALPHA_C * x23.y);
    __half2 h01 = __floats2half2_rn(o0, o1);
    __half2 h23 = __floats2half2_rn(o2, o3);
    *(uint2*)(f + (size_t)w * DH + lane * 4) = make_uint2(*(uint32_t*)&h01, *(uint32_t*)&h23);
}

// ---------------- GEMM: 2-term fp16 MMA (R15 tiling + A-tile register prefetch) ----------------
// C[n,NW] = A[n,128] @ B[128,NW] + bias. B = Bhi + Blo (fp16 split, ~22 mantissa bits).
// AFP32: stage A from fp32 (round to fp16, no prefetch). !AFP32: A fp16, next tile
// prefetched into registers during compute. WMODE: 0 fp32 C; 2 fp16 C16.
template <int NW, bool RELU, int WMODE, bool AFP32>
__global__ void __launch_bounds__(256) gemm_f16a_kernel(const void* __restrict__ Avoid,
                                                        const float* __restrict__ B,
                                                        const float* __restrict__ bias,
                                                        float* __restrict__ C,
                                                        __half* __restrict__ C16, int n) {
    constexpr int AW = 68;
    constexpr int BW = 68;
    constexpr int NT = NW / 32;
    extern __shared__ uint32_t smu[];
    uint32_t* As  = smu;                 // 64 x 68 (fp16 pairs)
    uint32_t* Bhi = As + 64 * AW;        // NW cols x 68 ([col][kword], fp16)
    uint32_t* Blo = Bhi + NW * BW;

    int tid = threadIdx.x;

    // stage + fp16-split B once, [col][k]
    {
        __half* BhiH = (__half*)Bhi;
        __half* BloH = (__half*)Blo;
#pragma unroll
        for (int i = 0; i < NW / 2; i++) {
            int idx = tid + i * 256;
            int k   = idx / NW;
            int col = idx % NW;
            float v = B[(size_t)k * NW + col];
            __half h, l;
            fp16_split(v, h, l);
            BhiH[col * (BW * 2) + k] = h;
            BloH[col * (BW * 2) + k] = l;
        }
    }

    int warp = tid >> 5, lane = tid & 31;
    int gid  = lane >> 2, tig = lane & 3;
    int wm   = warp & 1;
    int wn   = warp >> 1;
    int a_row = (lane & 7) + ((lane >> 3) & 1) * 8;
    int a_kx  = (lane >> 4) * 4;
    int b_col = wn * (NW / 4) + (lane & 7) + ((lane >> 4) & 1) * 8;
    int b_kx  = ((lane >> 3) & 1) * 4;
    uint32_t b_off = (uint32_t)(b_col * BW + b_kx) * 4u;

    uint32_t sAs  = (uint32_t)__cvta_generic_to_shared(As);
    uint32_t sBhi = (uint32_t)__cvta_generic_to_shared(Bhi);
    uint32_t sBlo = (uint32_t)__cvta_generic_to_shared(Blo);

    const uint4* A4h = (const uint4*)Avoid;

    // ---- register prefetch state (fp16-A path): 4 uint4 per thread ----
    uint4 pf[4];
    if (!AFP32) {
        int mb0 = blockIdx.x;
        if (mb0 * 64 < n) {
            size_t base = (size_t)(mb0 * 64) * 16;
#pragma unroll
            for (int i = 0; i < 4; i++) {
                int idx = tid + i * 256;
                int row = idx >> 4;
                pf[i] = (mb0 * 64 + row < n) ? A4h[base + idx] : make_uint4(0u, 0u, 0u, 0u);
            }
        }
    }

    for (int mb = blockIdx.x; mb * 64 < n; mb += gridDim.x) {
        int m0 = mb * 64;
        __syncthreads();
        if (AFP32) {
            // A fp32 -> fp16 rounded into smem (no prefetch)
            const float4* A4 = (const float4*)Avoid;
            size_t base4 = (size_t)m0 * (DH / 4);
#pragma unroll
            for (int i = 0; i < 8; i++) {
                int idx = tid + i * 256;      // 0..2047 float4s
                int row = idx >> 5;
                int c4  = idx & 31;
                float4 v = (m0 + row < n) ? A4[base4 + idx] : make_float4(0.f, 0.f, 0.f, 0.f);
                __half2 p0 = __floats2half2_rn(v.x, v.y);
                __half2 p1 = __floats2half2_rn(v.z, v.w);
                As[row * AW + c4 * 2]     = *(uint32_t*)&p0;
                As[row * AW + c4 * 2 + 1] = *(uint32_t*)&p1;
            }
        } else {
            // store prefetched A regs to smem
#pragma unroll
            for (int i = 0; i < 4; i++) {
                int idx = tid + i * 256;
                int row = idx >> 4;
                int c8  = idx & 15;
                *(uint4*)&As[row * AW + c8 * 4] = pf[i];
            }
        }
        __syncthreads();

        // issue next tile's global loads (complete under the MMA compute below)
        if (!AFP32) {
            int mbn = mb + gridDim.x;
            if (mbn * 64 < n) {
                size_t base = (size_t)(mbn * 64) * 16;
#pragma unroll
                for (int i = 0; i < 4; i++) {
                    int idx = tid + i * 256;
                    int row = idx >> 4;
                    pf[i] = (mbn * 64 + row < n) ? A4h[base + idx] : make_uint4(0u, 0u, 0u, 0u);
                }
            }
        }

        float acc[2][NT][4];
#pragma unroll
        for (int mt = 0; mt < 2; mt++)
#pragma unroll
            for (int nt = 0; nt < NT; nt++)
#pragma unroll
                for (int q = 0; q < 4; q++) acc[mt][nt][q] = 0.f;

#pragma unroll
        for (int k0 = 0; k0 < DH; k0 += 16) {
            uint32_t kb = (uint32_t)(k0 >> 1) * 4u;
            uint32_t a[2][4];
#pragma unroll
            for (int mt = 0; mt < 2; mt++) {
                uint32_t ao = (uint32_t)((wm * 32 + mt * 16 + a_row) * AW + a_kx) * 4u + kb;
                ldsm_x4(sAs + ao, a[mt]);
            }
#pragma unroll
            for (int p = 0; p < NT / 2; p++) {
                uint32_t bo = b_off + (uint32_t)(p * 16 * BW) * 4u + kb;
                uint32_t bh[4], bl[4];
                ldsm_x4(sBhi + bo, bh);
                ldsm_x4(sBlo + bo, bl);
#pragma unroll
                for (int mt = 0; mt < 2; mt++) {
                    mma16h(acc[mt][2 * p],     a[mt], bh[0], bh[1]);
                    mma16h(acc[mt][2 * p],     a[mt], bl[0], bl[1]);
                    mma16h(acc[mt][2 * p + 1], a[mt], bh[2], bh[3]);
                    mma16h(acc[mt][2 * p + 1], a[mt], bl[2], bl[3]);
                }
            }
        }

#pragma unroll
        for (int mt = 0; mt < 2; mt++) {
            int r0 = m0 + wm * 32 + mt * 16 + gid;
            int r1 = r0 + 8;
#pragma unroll
            for (int nt = 0; nt < NT; nt++) {
                int nc0 = wn * (NW / 4) + nt * 8 + tig * 2;
                float bv0 = bias[nc0], bv1 = bias[nc0 + 1];
                float v0 = acc[mt][nt][0] + bv0;
                float v1 = acc[mt][nt][1] + bv1;
                float v2 = acc[mt][nt][2] + bv0;
                float v3 = acc[mt][nt][3] + bv1;
                if (RELU) {
                    v0 = fmaxf(v0, 0.f); v1 = fmaxf(v1, 0.f);
                    v2 = fmaxf(v2, 0.f); v3 = fmaxf(v3, 0.f);
                }
                if (r0 < n) {
                    if (WMODE != 2) *(float2*)&C[(size_t)r0 * NW + nc0] = make_float2(v0, v1);
                    if (WMODE != 0) *(__half2*)&C16[(size_t)r0 * NW + nc0] = __floats2half2_rn(v0, v1);
                }
                if (r1 < n) {
                    if (WMODE != 2) *(float2*)&C[(size_t)r1 * NW + nc0] = make_float2(v2, v3);
                    if (WMODE != 0) *(__half2*)&C16[(size_t)r1 * NW + nc0] = __floats2half2_rn(v2, v3);
                }
            }
        }
    }
}

// ---------------- launch ----------------
extern "C" void kernel_launch(void* const* d_in, const int* in_sizes, int n_in,
                              void* d_out, int out_size) {
    const float* feat = (const float*)d_in[0];
    const int*   src  = (const int*)  d_in[1];
    const int*   dst  = (const int*)  d_in[2];
    const float* w1   = (const float*)d_in[3];
    const float* b1   = (const float*)d_in[4];
    const float* cw1  = (const float*)d_in[5];
    const float* cb1  = (const float*)d_in[6];
    const float* cw2  = (const float*)d_in[7];
    const float* cb2  = (const float*)d_in[8];
    const float* w2   = (const float*)d_in[9];
    const float* b2   = (const float*)d_in[10];
    float* out = (float*)d_out;

    int n = in_sizes[0] / DH;   // 100000
    int E = in_sizes[1];        // 1600000

    void *p_xh0, *p_xh1, *p_f16, *p_wp1, *p_wf, *p_bf;
    cudaGetSymbolAddress(&p_xh0, g_xh0);
    cudaGetSymbolAddress(&p_xh1, g_xh1);
    cudaGetSymbolAddress(&p_f16, g_f16);
    cudaGetSymbolAddress(&p_wp1, g_wp1);
    cudaGetSymbolAddress(&p_wf,  g_wf);
    cudaGetSymbolAddress(&p_bf,  g_bf);

    constexpr int SMEM_128 = (64 * 68 + 2 * 128 * 68) * 4;  // 87040 -> 2 blocks/SM
    constexpr int SMEM_64  = (64 * 68 + 2 * 64 * 68) * 4;   // 52224 -> 4 blocks/SM
    cudaFuncSetAttribute(gemm_f16a_kernel<128, true, 2, true>,
                         cudaFuncAttributeMaxDynamicSharedMemorySize, SMEM_128);
    cudaFuncSetAttribute(gemm_f16a_kernel<128, true, 2, false>,
                         cudaFuncAttributeMaxDynamicSharedMemorySize, SMEM_128);
    cudaFuncSetAttribute(gemm_f16a_kernel<64, false, 0, false>,
                         cudaFuncAttributeMaxDynamicSharedMemorySize, SMEM_64);

    int nb   = (n + 255) / 256;
    int eb   = (E + 255) / 256;
    int sb   = (n * 32 + 255) / 256;    // spmm: warp per row
    int nblk = (n + 255) / 256;
    const int PG2 = 296;   // 2 blocks/SM persistent grid
    const int PG4 = 592;   // 4 blocks/SM

    // One-time stream/event infra (created on the first, uncaptured call).
    static cudaStream_t s_csr = nullptr;
    static cudaEvent_t  ev_fork = nullptr, ev_join = nullptr;
    if (s_csr == nullptr) {
        cudaStreamCreateWithFlags(&s_csr, cudaStreamNonBlocking);
        cudaEventCreateWithFlags(&ev_fork, cudaEventDisableTiming);
        cudaEventCreateWithFlags(&ev_join, cudaEventDisableTiming);
    }

    // ---- fork: CSR build chain concurrent with prep+fc1 ----
    cudaEventRecord(ev_fork, 0);
    cudaStreamWaitEvent(s_csr, ev_fork, 0);

    zero_deg_kernel<<<nb, 256, 0, s_csr>>>(n);
    deg_kernel<<<eb, 256, 0, s_csr>>>(src, dst, E);
    rs_blocksum_kernel<<<nblk, 256, 0, s_csr>>>(n);
    scan_sums_kernel<<<1, 512, 0, s_csr>>>(nblk, n);
    writeptr_kernel<<<nblk, 256, 0, s_csr>>>(n);
    fill_kernel<<<eb, 256, 0, s_csr>>>(src, dst, E);
    cudaEventRecord(ev_join, s_csr);

    // branch A: weight prep + fc1 -> xh0 fp16  [fp32 A rounded to fp16, 2-term fp16 MMA]
    prep_weights_kernel<<<DH, DH>>>(cw1, cw2, w2, cb2, b2);
    gemm_f16a_kernel<128, true, 2, true><<<PG2, 256, SMEM_128>>>(feat, w1, b1,
        (float*)nullptr, (__half*)p_xh0, n);

    // ---- join ----
    cudaStreamWaitEvent(0, ev_join, 0);

    // conv1 SpMM: gather xh0, residual xh0 -> f16
    spmm_kernel<<<sb, 256>>>((const __half*)p_xh0, (const __half*)p_xh0, (__half*)p_f16, n);

    // conv1 linear: xh1 = relu(f1 @ W1' + cb1)  [A prefetched]
    gemm_f16a_kernel<128, true, 2, false><<<PG2, 256, SMEM_128>>>((const void*)p_f16,
        (const float*)p_wp1, cb1, (float*)nullptr, (__half*)p_xh1, n);

    // conv2 SpMM: gather xh1, residual xh0 -> f16
    spmm_kernel<<<sb, 256>>>((const __half*)p_xh1, (const __half*)p_xh0, (__half*)p_f16, n);

    // conv2+fc2: out = f2 @ Wf + bf  [A prefetched]
    gemm_f16a_kernel<64, false, 0, false><<<PG4, 256, SMEM_64>>>((const void*)p_f16,
        (const float*)p_wf, (const float*)p_bf, out, (__half*)nullptr, n);
}